// round 6
// baseline (speedup 1.0000x reference)
#include <cuda_runtime.h>

// Problem constants (fixed by setup_inputs)
#define NQ      512
#define NC      8000
#define DNUM    6
#define DCAT    20
#define NBINS   50
#define DOUT    10
#define CHUNK   1000
#define NCHUNKS 8
#define CPAD    1024
#define NCPAD   (NCHUNKS * CPAD)   // 8192
#define NENT    (NCPAD + NQ)       // 8704

// Collapsed encoding: 6 bin-sum (G) dims + 20 cat + 2 zero pads = 28 dims,
// stored as 14 float2 pairs for packed f32x2 math. Candidate side is stored
// NEGATED so |x - c| = |x + cneg| needs only add.rn.f32x2 + sign-clear.
#define D2   14
#define TQ   16
#define TC   256

#define PADVAL 1e7f

typedef unsigned long long ull;

// Scratch (device globals; no allocations allowed)
__device__ float2 g_c2[D2][NCPAD];   // negated candidate encodings, chunk-padded
__device__ float2 g_x2[D2][NQ];      // query encodings
__device__ int    g_y[NCPAD];
__device__ float  g_logits[NCHUNKS][NQ][DOUT];
__device__ float  g_lse[NCHUNKS][NQ];

__device__ __forceinline__ ull f32x2_add(ull a, ull b) {
    ull r;
    asm("add.rn.f32x2 %0, %1, %2;" : "=l"(r) : "l"(a), "l"(b));
    return r;
}

// ---------------------------------------------------------------------------
// Encoder. Range A: (entity, feature, slice-of-10-bins) work items, 255-thread
// blocks = 51 exact 5-slice groups, smem combine (partials are exact integers,
// order-free). Range B/C: cat transpose (+negate for candidates), pads, labels.
// Bin math uses explicit IEEE rn intrinsics to bit-match XLA's unfused ops.
// Label dtype detected at runtime (jax randint(int64) silently yields int32
// without x64): int64 labels 0..9 have all odd 32-bit words zero.
// ---------------------------------------------------------------------------
#define NSLICE  5
#define SLICEB  (NBINS / NSLICE)                 // 10
#define EBLK    255
#define ABLOCKS ((NENT * DNUM * NSLICE) / EBLK)  // 261120/255 = 1024 exact
#define BITEMS  (NCPAD + NQ)                     // 8704
#define BBLOCKS ((BITEMS + EBLK - 1) / EBLK)     // 35

__global__ void encode_kernel(const float* __restrict__ x_num,
                              const float* __restrict__ x_cat,
                              const float* __restrict__ c_num,
                              const float* __restrict__ c_cat,
                              const void*  __restrict__ y_raw,
                              const float* __restrict__ delta,
                              const float* __restrict__ u) {
    __shared__ float s_d[DNUM * NBINS], s_u[DNUM * NBINS];
    __shared__ float s_p[EBLK];
    const int tid = threadIdx.x;
    for (int i = tid; i < DNUM * NBINS; i += EBLK) {
        s_d[i] = delta[i];
        s_u[i] = u[i];
    }
    __syncthreads();

    if (blockIdx.x < ABLOCKS) {
        const int w  = blockIdx.x * EBLK + tid;
        const int ej = w / NSLICE, s = w - ej * NSLICE;
        const int j  = ej / NENT;
        const int e  = ej - j * NENT;
        bool valid = true;
        float x = 0.f;
        if (e < NCPAD) {
            const int ch = e >> 10, idx = e & (CPAD - 1);
            if (idx < CHUNK) x = c_num[(ch * CHUNK + idx) * DNUM + j];
            else valid = false;
        } else {
            x = x_num[(e - NCPAD) * DNUM + j];
        }
        float p = 0.f;
        if (valid) {
            const int b0 = j * NBINS + s * SLICEB;
#pragma unroll
            for (int b = 0; b < SLICEB; ++b) {
                const float dl = s_d[b0 + b];
                const float uu = s_u[b0 + b];
                p = __fadd_rn(p, ceilf(__fdiv_rn(__fsub_rn(x, __fmul_rn(uu, dl)), dl)));
            }
        }
        s_p[tid] = p;
        __syncthreads();
        if (s == 0) {
            float g = s_p[tid] + s_p[tid + 1] + s_p[tid + 2] + s_p[tid + 3] + s_p[tid + 4];
            if (e < NCPAD) {
                ((float*)&g_c2[j >> 1][e])[j & 1] = valid ? -g : -PADVAL;
            } else {
                ((float*)&g_x2[j >> 1][e - NCPAD])[j & 1] = g;
            }
        }
        return;
    }

    const int item = (blockIdx.x - ABLOCKS) * EBLK + tid;
    if (item < NCPAD) {
        const int c = item;
        const int ch = c >> 10, idx = c & (CPAD - 1);
        if (idx < CHUNK) {
            const int src = ch * CHUNK + idx;
#pragma unroll
            for (int k2 = 0; k2 < DCAT / 2; ++k2)
                g_c2[3 + k2][c] = make_float2(-c_cat[src * DCAT + 2 * k2],
                                              -c_cat[src * DCAT + 2 * k2 + 1]);
            g_c2[13][c] = make_float2(0.f, 0.f);
            const int* p32 = (const int*)y_raw;
            int z = 1;
#pragma unroll
            for (int i = 0; i < 32; ++i)
                if (p32[2 * i + 1] != 0) z = 0;
            const long long* p64 = (const long long*)y_raw;
            g_y[c] = z ? (int)p64[src] : p32[src];
        } else {
#pragma unroll
            for (int d = 3; d < D2; ++d) g_c2[d][c] = make_float2(-PADVAL, -PADVAL);
            g_y[c] = 0;
        }
    } else if (item < BITEMS) {
        const int q = item - NCPAD;
#pragma unroll
        for (int k2 = 0; k2 < DCAT / 2; ++k2)
            g_x2[3 + k2][q] = make_float2(x_cat[q * DCAT + 2 * k2],
                                          x_cat[q * DCAT + 2 * k2 + 1]);
        g_x2[13][q] = make_float2(0.f, 0.f);
    }
}

// ---------------------------------------------------------------------------
// Main kernel: one block per (16-query tile, chunk). Block = (64, 4) threads.
// Each thread owns a 4q x 4c register tile of packed f32x2 accumulators.
// No online max (dist >= 0 so exp(-dist) <= 1 cannot overflow); lse = log(sum)
// which equals the reference logsumexp to fp32 rounding.
// ---------------------------------------------------------------------------
__global__ __launch_bounds__(256, 2) void nca_main_kernel() {
    const int tc  = threadIdx.x;                 // 0..63
    const int tq  = threadIdx.y;                 // 0..3
    const int lid = tq * 64 + tc;
    const int q0  = blockIdx.x * TQ;
    const int cb0 = blockIdx.y * CPAD;

    __shared__ float2 x_s[D2][TQ];               // 1.75 KB
    __shared__ float2 c_s[D2][TC];               // 28 KB
    __shared__ float  red[4][2][4][11];

    // Stage query pairs once (112 float4)
    if (lid < 112) {
        int dd = lid >> 3, t = lid & 7;
        ((float4*)&x_s[dd][0])[t] = ((const float4*)&g_x2[dd][q0])[t];
    }

    float s[4], lg[4][10];
#pragma unroll
    for (int qi = 0; qi < 4; ++qi) {
        s[qi] = 0.f;
#pragma unroll
        for (int k = 0; k < DOUT; ++k) lg[qi][k] = 0.f;
    }

    const ull SMASK = 0x7fffffff7fffffffULL;

    for (int t = 0; t < 4; ++t) {
        const int cbase = cb0 + t * TC;
        __syncthreads();   // protect c_s reuse (1st iter: also x_s store)
        // stage 14 x 256 float2 slab (1792 float4)
#pragma unroll
        for (int k = 0; k < 7; ++k) {
            int idx = lid + 256 * k;
            int dd = idx >> 7, jj = idx & 127;
            ((float4*)&c_s[dd][0])[jj] = ((const float4*)&g_c2[dd][cbase])[jj];
        }
        __syncthreads();

        int yv[4];
#pragma unroll
        for (int ci = 0; ci < 4; ++ci) yv[ci] = g_y[cbase + tc * 4 + ci];

        ull acc[4][4];
#pragma unroll
        for (int qi = 0; qi < 4; ++qi)
#pragma unroll
            for (int ci = 0; ci < 4; ++ci) acc[qi][ci] = 0ULL;

#pragma unroll
        for (int dd = 0; dd < D2; ++dd) {
            ulonglong2 xv0 = *(const ulonglong2*)&x_s[dd][tq * 4];
            ulonglong2 xv1 = *(const ulonglong2*)&x_s[dd][tq * 4 + 2];
            ulonglong2 cv0 = *(const ulonglong2*)&c_s[dd][tc * 4];
            ulonglong2 cv1 = *(const ulonglong2*)&c_s[dd][tc * 4 + 2];
            ull xa[4] = {xv0.x, xv0.y, xv1.x, xv1.y};
            ull ca[4] = {cv0.x, cv0.y, cv1.x, cv1.y};
#pragma unroll
            for (int qi = 0; qi < 4; ++qi)
#pragma unroll
                for (int ci = 0; ci < 4; ++ci) {
                    ull d = f32x2_add(xa[qi], ca[ci]);  // x + (-c) == x - c
                    d &= SMASK;                          // packed |.| (2x LOP3, alu pipe)
                    acc[qi][ci] = f32x2_add(acc[qi][ci], d);
                }
        }

        // Epilogue: one exp per pair, plain sums
#pragma unroll
        for (int qi = 0; qi < 4; ++qi)
#pragma unroll
            for (int ci = 0; ci < 4; ++ci) {
                ull a = acc[qi][ci];
                float lo = __uint_as_float((unsigned)a);
                float hi = __uint_as_float((unsigned)(a >> 32));
                float e = __expf(-(lo + hi));   // pad: exp(-2.8e8) -> 0
                s[qi] += e;
                int y = yv[ci];
#pragma unroll
                for (int k = 0; k < DOUT; ++k)
                    lg[qi][k] += (y == k) ? e : 0.f;
            }
    }

    // Warp-level plain-sum reduce across 32 lanes
#pragma unroll
    for (int off = 16; off >= 1; off >>= 1) {
#pragma unroll
        for (int qi = 0; qi < 4; ++qi) {
            s[qi] += __shfl_xor_sync(0xffffffffu, s[qi], off);
#pragma unroll
            for (int k = 0; k < DOUT; ++k)
                lg[qi][k] += __shfl_xor_sync(0xffffffffu, lg[qi][k], off);
        }
    }

    __syncthreads();
    if ((tc & 31) == 0) {
        int h = tc >> 5;
#pragma unroll
        for (int qi = 0; qi < 4; ++qi) {
            red[tq][h][qi][0] = s[qi];
#pragma unroll
            for (int k = 0; k < DOUT; ++k) red[tq][h][qi][1 + k] = lg[qi][k];
        }
    }
    __syncthreads();
    if (tc == 0) {
#pragma unroll
        for (int qi = 0; qi < 4; ++qi) {
            float S = red[tq][0][qi][0] + red[tq][1][qi][0];
            int q = q0 + tq * 4 + qi;
            g_lse[blockIdx.y][q] = logf(S);
#pragma unroll
            for (int k = 0; k < DOUT; ++k)
                g_logits[blockIdx.y][q][k] = red[tq][0][qi][1 + k] + red[tq][1][qi][1 + k];
        }
    }
}

// ---------------------------------------------------------------------------
__global__ void finalize_kernel(float* __restrict__ out) {
    int i = blockIdx.x * blockDim.x + threadIdx.x;
    if (i >= NQ * DOUT) return;
    int q = i / DOUT, k = i % DOUT;
    float lsum = 0.f, lse = 0.f;
#pragma unroll
    for (int ch = 0; ch < NCHUNKS; ++ch) {
        lsum += g_logits[ch][q][k];
        lse  += g_lse[ch][q];
    }
    out[i] = logf(lsum + 1e-8f) - lse;
}

// ---------------------------------------------------------------------------
extern "C" void kernel_launch(void* const* d_in, const int* in_sizes, int n_in,
                              void* d_out, int out_size) {
    const float* x_num = (const float*)d_in[0];
    const float* x_cat = (const float*)d_in[1];
    const float* c_num = (const float*)d_in[2];
    const float* c_cat = (const float*)d_in[3];
    const void*  c_y   = (const void*)d_in[4];
    const float* delta = (const float*)d_in[5];
    const float* u     = (const float*)d_in[6];
    float* out = (float*)d_out;

    encode_kernel<<<ABLOCKS + BBLOCKS, EBLK>>>(
        x_num, x_cat, c_num, c_cat, c_y, delta, u);
    nca_main_kernel<<<dim3(NQ / TQ, NCHUNKS), dim3(64, 4)>>>();
    finalize_kernel<<<(NQ * DOUT + 255) / 256, 256>>>(out);
}

// round 7
// speedup vs baseline: 1.0640x; 1.0640x over previous
#include <cuda_runtime.h>

// Problem constants (fixed by setup_inputs)
#define NQ      512
#define NC      8000
#define DNUM    6
#define DCAT    20
#define NBINS   50
#define DOUT    10
#define CHUNK   1000
#define NCHUNKS 8
#define CPAD    1024
#define NCPAD   (NCHUNKS * CPAD)   // 8192
#define NENT    (NCPAD + NQ)       // 8704

// Collapsed encoding: 6 bin-sum (G) dims + 20 cat + 2 zero pads = 28 dims,
// stored as 14 float2 pairs for packed FFMA2 math. Candidate side is stored
// NEGATED so |x - c| = |x*1 + cneg| via fma.rn.f32x2 + sign-clear AND.
#define D2   14
#define TQ   16
#define TC   256

#define PADVAL 1e7f

typedef unsigned long long ull;

// Scratch (device globals; no allocations allowed)
__device__ float2 g_c2[D2][NCPAD];   // negated candidate encodings, chunk-padded
__device__ float2 g_x2[D2][NQ];      // query encodings
__device__ int    g_y[NCPAD];
__device__ float  g_logits[NCHUNKS][NQ][DOUT];
__device__ float  g_lse[NCHUNKS][NQ];

// Packed dual-fp32 FMA (SASS FFMA2 — only reachable via PTX fma.rn.f32x2).
// a*1.0 + b gives bit-identical results to FADD rn (x*1.0 is exact).
__device__ __forceinline__ ull f32x2_fma(ull a, ull b, ull c) {
    ull r;
    asm("fma.rn.f32x2 %0, %1, %2, %3;" : "=l"(r) : "l"(a), "l"(b), "l"(c));
    return r;
}

// ---------------------------------------------------------------------------
// Encoder. Range A: (entity, feature, slice-of-10-bins) work items; delta/u
// read directly via __ldg (no smem staging); 5 exact-integer partials combined
// through smem (order-free). Range B/C: cat transpose (+negate for
// candidates), pads, labels. Bin math uses explicit IEEE rn intrinsics to
// bit-match XLA's unfused ops. Label dtype detected at runtime (jax
// randint(int64) silently yields int32 without x64): int64 labels 0..9 have
// all odd 32-bit words zero.
// ---------------------------------------------------------------------------
#define NSLICE  5
#define SLICEB  (NBINS / NSLICE)                 // 10
#define EBLK    255
#define ABLOCKS ((NENT * DNUM * NSLICE) / EBLK)  // 261120/255 = 1024 exact
#define BITEMS  (NCPAD + NQ)                     // 8704
#define BBLOCKS ((BITEMS + EBLK - 1) / EBLK)     // 35

__global__ void encode_kernel(const float* __restrict__ x_num,
                              const float* __restrict__ x_cat,
                              const float* __restrict__ c_num,
                              const float* __restrict__ c_cat,
                              const void*  __restrict__ y_raw,
                              const float* __restrict__ delta,
                              const float* __restrict__ u) {
    const int tid = threadIdx.x;

    if (blockIdx.x < ABLOCKS) {
        __shared__ float s_p[EBLK];
        const int w  = blockIdx.x * EBLK + tid;
        const int ej = w / NSLICE, s = w - ej * NSLICE;
        const int j  = ej / NENT;
        const int e  = ej - j * NENT;
        bool valid = true;
        float x = 0.f;
        if (e < NCPAD) {
            const int ch = e >> 10, idx = e & (CPAD - 1);
            if (idx < CHUNK) x = c_num[(ch * CHUNK + idx) * DNUM + j];
            else valid = false;
        } else {
            x = x_num[(e - NCPAD) * DNUM + j];
        }
        float p = 0.f;
        if (valid) {
            const int b0 = j * NBINS + s * SLICEB;
#pragma unroll
            for (int b = 0; b < SLICEB; ++b) {
                const float dl = __ldg(&delta[b0 + b]);
                const float uu = __ldg(&u[b0 + b]);
                p = __fadd_rn(p, ceilf(__fdiv_rn(__fsub_rn(x, __fmul_rn(uu, dl)), dl)));
            }
        }
        s_p[tid] = p;
        __syncthreads();
        if (s == 0) {
            float g = s_p[tid] + s_p[tid + 1] + s_p[tid + 2] + s_p[tid + 3] + s_p[tid + 4];
            if (e < NCPAD) {
                ((float*)&g_c2[j >> 1][e])[j & 1] = valid ? -g : -PADVAL;
            } else {
                ((float*)&g_x2[j >> 1][e - NCPAD])[j & 1] = g;
            }
        }
        return;
    }

    const int item = (blockIdx.x - ABLOCKS) * EBLK + tid;
    if (item < NCPAD) {
        const int c = item;
        const int ch = c >> 10, idx = c & (CPAD - 1);
        if (idx < CHUNK) {
            const int src = ch * CHUNK + idx;
#pragma unroll
            for (int k2 = 0; k2 < DCAT / 2; ++k2)
                g_c2[3 + k2][c] = make_float2(-c_cat[src * DCAT + 2 * k2],
                                              -c_cat[src * DCAT + 2 * k2 + 1]);
            g_c2[13][c] = make_float2(0.f, 0.f);
            const int* p32 = (const int*)y_raw;
            int z = 1;
#pragma unroll
            for (int i = 0; i < 32; ++i)
                if (p32[2 * i + 1] != 0) z = 0;
            const long long* p64 = (const long long*)y_raw;
            g_y[c] = z ? (int)p64[src] : p32[src];
        } else {
#pragma unroll
            for (int d = 3; d < D2; ++d) g_c2[d][c] = make_float2(-PADVAL, -PADVAL);
            g_y[c] = 0;
        }
    } else if (item < BITEMS) {
        const int q = item - NCPAD;
#pragma unroll
        for (int k2 = 0; k2 < DCAT / 2; ++k2)
            g_x2[3 + k2][q] = make_float2(x_cat[q * DCAT + 2 * k2],
                                          x_cat[q * DCAT + 2 * k2 + 1]);
        g_x2[13][q] = make_float2(0.f, 0.f);
    }
}

// ---------------------------------------------------------------------------
// Main kernel: one block per (16-query tile, chunk). Block = (64, 4) threads.
// Each thread owns a 4q x 4c register tile of packed f32x2 accumulators,
// driven by FFMA2 (fma pipe) + packed-abs LOP3 (alu pipe): both pipes loaded
// at ~50% each instead of fma at 100%. No online max needed (dist >= 0 so
// exp(-dist) <= 1 cannot overflow); lse = log(sum).
// ---------------------------------------------------------------------------
__global__ __launch_bounds__(256, 2) void nca_main_kernel() {
    const int tc  = threadIdx.x;                 // 0..63
    const int tq  = threadIdx.y;                 // 0..3
    const int lid = tq * 64 + tc;
    const int q0  = blockIdx.x * TQ;
    const int cb0 = blockIdx.y * CPAD;

    __shared__ float2 x_s[D2][TQ];               // 1.75 KB
    __shared__ float2 c_s[D2][TC];               // 28 KB
    __shared__ float  red[4][2][4][11];

    // Stage query pairs once (112 float4)
    if (lid < 112) {
        int dd = lid >> 3, t = lid & 7;
        ((float4*)&x_s[dd][0])[t] = ((const float4*)&g_x2[dd][q0])[t];
    }

    float s[4], lg[4][10];
#pragma unroll
    for (int qi = 0; qi < 4; ++qi) {
        s[qi] = 0.f;
#pragma unroll
        for (int k = 0; k < DOUT; ++k) lg[qi][k] = 0.f;
    }

    const ull SMASK = 0x7fffffff7fffffffULL;
    const ull ONE2  = 0x3f8000003f800000ULL;     // (1.0f, 1.0f)

    for (int t = 0; t < 4; ++t) {
        const int cbase = cb0 + t * TC;
        __syncthreads();   // protect c_s reuse (1st iter: also x_s store)
        // stage 14 x 256 float2 slab (1792 float4)
#pragma unroll
        for (int k = 0; k < 7; ++k) {
            int idx = lid + 256 * k;
            int dd = idx >> 7, jj = idx & 127;
            ((float4*)&c_s[dd][0])[jj] = ((const float4*)&g_c2[dd][cbase])[jj];
        }
        __syncthreads();

        int yv[4];
#pragma unroll
        for (int ci = 0; ci < 4; ++ci) yv[ci] = g_y[cbase + tc * 4 + ci];

        ull acc[4][4];
#pragma unroll
        for (int qi = 0; qi < 4; ++qi)
#pragma unroll
            for (int ci = 0; ci < 4; ++ci) acc[qi][ci] = 0ULL;

#pragma unroll
        for (int dd = 0; dd < D2; ++dd) {
            ulonglong2 xv0 = *(const ulonglong2*)&x_s[dd][tq * 4];
            ulonglong2 xv1 = *(const ulonglong2*)&x_s[dd][tq * 4 + 2];
            ulonglong2 cv0 = *(const ulonglong2*)&c_s[dd][tc * 4];
            ulonglong2 cv1 = *(const ulonglong2*)&c_s[dd][tc * 4 + 2];
            ull xa[4] = {xv0.x, xv0.y, xv1.x, xv1.y};
            ull ca[4] = {cv0.x, cv0.y, cv1.x, cv1.y};
#pragma unroll
            for (int qi = 0; qi < 4; ++qi)
#pragma unroll
                for (int ci = 0; ci < 4; ++ci) {
                    ull d = f32x2_fma(xa[qi], ONE2, ca[ci]);   // x*1 + (-c) == x - c
                    d &= SMASK;                                 // packed |.| (2x LOP3, alu)
                    acc[qi][ci] = f32x2_fma(d, ONE2, acc[qi][ci]);
                }
        }

        // Epilogue: one exp per pair, plain sums
#pragma unroll
        for (int qi = 0; qi < 4; ++qi)
#pragma unroll
            for (int ci = 0; ci < 4; ++ci) {
                ull a = acc[qi][ci];
                float lo = __uint_as_float((unsigned)a);
                float hi = __uint_as_float((unsigned)(a >> 32));
                float e = __expf(-(lo + hi));   // pad: exp(-2.8e8) -> 0
                s[qi] += e;
                int y = yv[ci];
#pragma unroll
                for (int k = 0; k < DOUT; ++k)
                    lg[qi][k] += (y == k) ? e : 0.f;
            }
    }

    // Warp-level plain-sum reduce across 32 lanes
#pragma unroll
    for (int off = 16; off >= 1; off >>= 1) {
#pragma unroll
        for (int qi = 0; qi < 4; ++qi) {
            s[qi] += __shfl_xor_sync(0xffffffffu, s[qi], off);
#pragma unroll
            for (int k = 0; k < DOUT; ++k)
                lg[qi][k] += __shfl_xor_sync(0xffffffffu, lg[qi][k], off);
        }
    }

    __syncthreads();
    if ((tc & 31) == 0) {
        int h = tc >> 5;
#pragma unroll
        for (int qi = 0; qi < 4; ++qi) {
            red[tq][h][qi][0] = s[qi];
#pragma unroll
            for (int k = 0; k < DOUT; ++k) red[tq][h][qi][1 + k] = lg[qi][k];
        }
    }
    __syncthreads();
    if (tc == 0) {
#pragma unroll
        for (int qi = 0; qi < 4; ++qi) {
            float S = red[tq][0][qi][0] + red[tq][1][qi][0];
            int q = q0 + tq * 4 + qi;
            g_lse[blockIdx.y][q] = logf(S);
#pragma unroll
            for (int k = 0; k < DOUT; ++k)
                g_logits[blockIdx.y][q][k] = red[tq][0][qi][1 + k] + red[tq][1][qi][1 + k];
        }
    }
}

// ---------------------------------------------------------------------------
__global__ void finalize_kernel(float* __restrict__ out) {
    int i = blockIdx.x * blockDim.x + threadIdx.x;
    if (i >= NQ * DOUT) return;
    int q = i / DOUT, k = i % DOUT;
    float lsum = 0.f, lse = 0.f;
#pragma unroll
    for (int ch = 0; ch < NCHUNKS; ++ch) {
        lsum += g_logits[ch][q][k];
        lse  += g_lse[ch][q];
    }
    out[i] = logf(lsum + 1e-8f) - lse;
}

// ---------------------------------------------------------------------------
extern "C" void kernel_launch(void* const* d_in, const int* in_sizes, int n_in,
                              void* d_out, int out_size) {
    const float* x_num = (const float*)d_in[0];
    const float* x_cat = (const float*)d_in[1];
    const float* c_num = (const float*)d_in[2];
    const float* c_cat = (const float*)d_in[3];
    const void*  c_y   = (const void*)d_in[4];
    const float* delta = (const float*)d_in[5];
    const float* u     = (const float*)d_in[6];
    float* out = (float*)d_out;

    encode_kernel<<<ABLOCKS + BBLOCKS, EBLK>>>(
        x_num, x_cat, c_num, c_cat, c_y, delta, u);
    nca_main_kernel<<<dim3(NQ / TQ, NCHUNKS), dim3(64, 4)>>>();
    finalize_kernel<<<(NQ * DOUT + 255) / 256, 256>>>(out);
}

// round 12
// speedup vs baseline: 1.0727x; 1.0082x over previous
#include <cuda_runtime.h>

// Problem constants (fixed by setup_inputs)
#define NQ      512
#define NC      8000
#define DNUM    6
#define DCAT    20
#define NBINS   50
#define DOUT    10
#define CHUNK   1000
#define NCHUNKS 8
#define CPAD    1024
#define NCPAD   (NCHUNKS * CPAD)   // 8192
#define NENT    (NCPAD + NQ)       // 8704

// Collapsed encoding: 6 bin-sum (G) dims + 20 cat = 26 real dims, plus
// slot 26 = per-entity sum S (for the min-trick). L1 dist via
//   sum|x-c| = Sx + Sc - 2*sum(min(x,c))
// G dims are integers (exact); cat part adds ~1e-4 abs error (tolerance 1e-3).
#define DDIM 26
#define DROW 27
#define TQ   16
#define TC   256

#define PADVAL 1e7f

// Scratch (device globals; no allocations allowed)
__device__ float g_cE[DROW][NCPAD];  // candidate encodings + Sc, chunk-padded
__device__ float g_xE[DROW][NQ];     // query encodings + Sx
__device__ int   g_y[NCPAD];
__device__ float g_logits[NCHUNKS][NQ][DOUT];
__device__ float g_lse[NCHUNKS][NQ];

// ---------------------------------------------------------------------------
// Encoder. Range A: (entity, feature, slice-of-10-bins) work items with a
// fast-division path: q = t * rcp_rn(d); ceil(q) == ceil(rn(t/d)) unless q is
// within ~5e-7*|q| of an integer, in which case we redo with exact __fdiv_rn.
// 5 exact-integer partials combined through smem (order-free). Range B/C:
// cat transpose, pads, labels. Label dtype detected at runtime (jax
// randint(int64) silently yields int32 without x64): int64 labels 0..9 have
// all odd 32-bit words zero.
// ---------------------------------------------------------------------------
#define NSLICE  5
#define SLICEB  (NBINS / NSLICE)                 // 10
#define EBLK    255
#define ABLOCKS ((NENT * DNUM * NSLICE) / EBLK)  // 1024 exact
#define BITEMS  (NCPAD + NQ)                     // 8704
#define BBLOCKS ((BITEMS + EBLK - 1) / EBLK)     // 35

__global__ void encode_kernel(const float* __restrict__ x_num,
                              const float* __restrict__ x_cat,
                              const float* __restrict__ c_num,
                              const float* __restrict__ c_cat,
                              const void*  __restrict__ y_raw,
                              const float* __restrict__ delta,
                              const float* __restrict__ u) {
    const int tid = threadIdx.x;

    if (blockIdx.x < ABLOCKS) {
        __shared__ float s_p[EBLK];
        const int w  = blockIdx.x * EBLK + tid;
        const int ej = w / NSLICE, s = w - ej * NSLICE;
        const int j  = ej / NENT;
        const int e  = ej - j * NENT;
        bool valid = true;
        float x = 0.f;
        if (e < NCPAD) {
            const int ch = e >> 10, idx = e & (CPAD - 1);
            if (idx < CHUNK) x = c_num[(ch * CHUNK + idx) * DNUM + j];
            else valid = false;
        } else {
            x = x_num[(e - NCPAD) * DNUM + j];
        }
        float p = 0.f;
        if (valid) {
            const int b0 = j * NBINS + s * SLICEB;
#pragma unroll
            for (int b = 0; b < SLICEB; ++b) {
                const float dl = __ldg(&delta[b0 + b]);
                const float uu = __ldg(&u[b0 + b]);
                const float t  = __fsub_rn(x, __fmul_rn(uu, dl));
                const float q  = __fmul_rn(t, __frcp_rn(dl));
                const float r  = rintf(q);
                float cl;
                if (fabsf(__fsub_rn(q, r)) < __fmaf_rn(fabsf(q), 5e-7f, 1e-30f)) {
                    cl = ceilf(__fdiv_rn(t, dl));   // exact slow path (rare)
                } else {
                    cl = ceilf(q);                  // provably equal to exact
                }
                p = __fadd_rn(p, cl);
            }
        }
        s_p[tid] = p;
        __syncthreads();
        if (s == 0) {
            float g = s_p[tid] + s_p[tid + 1] + s_p[tid + 2] + s_p[tid + 3] + s_p[tid + 4];
            if (e < NCPAD) g_cE[j][e] = valid ? g : PADVAL;
            else           g_xE[j][e - NCPAD] = g;
        }
        return;
    }

    const int item = (blockIdx.x - ABLOCKS) * EBLK + tid;
    if (item < NCPAD) {
        const int c = item;
        const int ch = c >> 10, idx = c & (CPAD - 1);
        if (idx < CHUNK) {
            const int src = ch * CHUNK + idx;
#pragma unroll
            for (int k = 0; k < DCAT; ++k)
                g_cE[DNUM + k][c] = c_cat[src * DCAT + k];
            const int* p32 = (const int*)y_raw;
            int z = 1;
#pragma unroll
            for (int i = 0; i < 32; ++i)
                if (p32[2 * i + 1] != 0) z = 0;
            const long long* p64 = (const long long*)y_raw;
            g_y[c] = z ? (int)p64[src] : p32[src];
        } else {
#pragma unroll
            for (int k = 0; k < DCAT; ++k) g_cE[DNUM + k][c] = PADVAL;
            g_y[c] = 0;
        }
    } else if (item < BITEMS) {
        const int q = item - NCPAD;
#pragma unroll
        for (int k = 0; k < DCAT; ++k)
            g_xE[DNUM + k][q] = x_cat[q * DCAT + k];
    }
}

// ---------------------------------------------------------------------------
// Prep: per-entity dim-sums into slot 26 (coalesced column reads).
// Pad candidates get Sc ~ 2.6e8 -> dist huge -> weight 0.
// ---------------------------------------------------------------------------
__global__ void prep_kernel() {
    const int e = blockIdx.x * blockDim.x + threadIdx.x;
    if (e < NCPAD) {
        float s = 0.f;
#pragma unroll
        for (int d = 0; d < DDIM; ++d) s += g_cE[d][e];
        g_cE[DDIM][e] = s;
    } else if (e < BITEMS) {
        const int q = e - NCPAD;
        float s = 0.f;
#pragma unroll
        for (int d = 0; d < DDIM; ++d) s += g_xE[d][q];
        g_xE[DDIM][q] = s;
    }
}

// ---------------------------------------------------------------------------
// Main kernel: one block per (16-query tile, chunk). Block = (64, 4) threads.
// Each thread owns a 4q x 4c register tile. Mainloop: acc += min(x, c) —
// FMNMX on the alu pipe + FADD on the fma pipe (balanced, ~2x vs pure-fma).
// dist = fmaf(acc, -2, Sx + Sc); one exp per pair; class partials only
// (lse denominator = sum of class sums, computed at the end).
// ---------------------------------------------------------------------------
__global__ __launch_bounds__(256, 2) void nca_main_kernel() {
    const int tc  = threadIdx.x;                 // 0..63
    const int tq  = threadIdx.y;                 // 0..3
    const int lid = tq * 64 + tc;
    const int q0  = blockIdx.x * TQ;
    const int cb0 = blockIdx.y * CPAD;

    __shared__ float x_s[DROW][TQ];              // 1.7 KB (27 rows x 16)
    __shared__ float c_s[DROW][TC];              // 27 KB
    __shared__ float red[4][2][4][10];

    // Stage query slab once (108 float4)
    if (lid < DROW * (TQ / 4)) {
        int dd = lid >> 2, t = lid & 3;
        ((float4*)&x_s[dd][0])[t] = ((const float4*)&g_xE[dd][q0])[t];
    }

    float lg[4][10];
#pragma unroll
    for (int qi = 0; qi < 4; ++qi)
#pragma unroll
        for (int k = 0; k < DOUT; ++k) lg[qi][k] = 0.f;

    for (int t = 0; t < 4; ++t) {
        const int cbase = cb0 + t * TC;
        __syncthreads();   // protect c_s reuse (1st iter: also x_s store)
        // stage 27 x 256 slab (1728 float4)
#pragma unroll
        for (int k = 0; k < 7; ++k) {
            int idx = lid + 256 * k;
            if (idx < DROW * (TC / 4)) {
                int dd = idx >> 6, jj = idx & 63;
                ((float4*)&c_s[dd][0])[jj] = ((const float4*)&g_cE[dd][cbase])[jj];
            }
        }
        __syncthreads();

        int yv[4];
#pragma unroll
        for (int ci = 0; ci < 4; ++ci) yv[ci] = g_y[cbase + tc * 4 + ci];

        float acc[4][4];
#pragma unroll
        for (int qi = 0; qi < 4; ++qi)
#pragma unroll
            for (int ci = 0; ci < 4; ++ci) acc[qi][ci] = 0.f;

#pragma unroll
        for (int dd = 0; dd < DDIM; ++dd) {
            float4 xv = *(const float4*)&x_s[dd][tq * 4];
            float4 cv = *(const float4*)&c_s[dd][tc * 4];
            float xa[4] = {xv.x, xv.y, xv.z, xv.w};
            float ca[4] = {cv.x, cv.y, cv.z, cv.w};
#pragma unroll
            for (int qi = 0; qi < 4; ++qi)
#pragma unroll
                for (int ci = 0; ci < 4; ++ci)
                    acc[qi][ci] += fminf(xa[qi], ca[ci]);   // FMNMX(alu)+FADD(fma)
        }

        // Epilogue: dist = Sx + Sc - 2*acc, one exp per pair
        float4 sxv = *(const float4*)&x_s[DDIM][tq * 4];
        float4 scv = *(const float4*)&c_s[DDIM][tc * 4];
        float Sx[4] = {sxv.x, sxv.y, sxv.z, sxv.w};
        float Sc[4] = {scv.x, scv.y, scv.z, scv.w};
#pragma unroll
        for (int ci = 0; ci < 4; ++ci) {
            int y = yv[ci];
#pragma unroll
            for (int qi = 0; qi < 4; ++qi) {
                float P = Sx[qi] + Sc[ci];
                float dist = __fmaf_rn(acc[qi][ci], -2.f, P);
                float e = __expf(-dist);        // pad: exp(-2.6e8) -> 0
#pragma unroll
                for (int k = 0; k < DOUT; ++k)
                    lg[qi][k] += (y == k) ? e : 0.f;
            }
        }
    }

    // Warp-level plain-sum reduce across 32 lanes
#pragma unroll
    for (int off = 16; off >= 1; off >>= 1) {
#pragma unroll
        for (int qi = 0; qi < 4; ++qi)
#pragma unroll
            for (int k = 0; k < DOUT; ++k)
                lg[qi][k] += __shfl_xor_sync(0xffffffffu, lg[qi][k], off);
    }

    __syncthreads();
    if ((tc & 31) == 0) {
        int h = tc >> 5;
#pragma unroll
        for (int qi = 0; qi < 4; ++qi)
#pragma unroll
            for (int k = 0; k < DOUT; ++k) red[tq][h][qi][k] = lg[qi][k];
    }
    __syncthreads();
    if (tc == 0) {
#pragma unroll
        for (int qi = 0; qi < 4; ++qi) {
            int q = q0 + tq * 4 + qi;
            float S = 0.f;
#pragma unroll
            for (int k = 0; k < DOUT; ++k) {
                float v = red[tq][0][qi][k] + red[tq][1][qi][k];
                g_logits[blockIdx.y][q][k] = v;
                S += v;
            }
            g_lse[blockIdx.y][q] = logf(S);
        }
    }
}

// ---------------------------------------------------------------------------
__global__ void finalize_kernel(float* __restrict__ out) {
    int i = blockIdx.x * blockDim.x + threadIdx.x;
    if (i >= NQ * DOUT) return;
    int q = i / DOUT, k = i % DOUT;
    float lsum = 0.f, lse = 0.f;
#pragma unroll
    for (int ch = 0; ch < NCHUNKS; ++ch) {
        lsum += g_logits[ch][q][k];
        lse  += g_lse[ch][q];
    }
    out[i] = logf(lsum + 1e-8f) - lse;
}

// ---------------------------------------------------------------------------
extern "C" void kernel_launch(void* const* d_in, const int* in_sizes, int n_in,
                              void* d_out, int out_size) {
    const float* x_num = (const float*)d_in[0];
    const float* x_cat = (const float*)d_in[1];
    const float* c_num = (const float*)d_in[2];
    const float* c_cat = (const float*)d_in[3];
    const void*  c_y   = (const void*)d_in[4];
    const float* delta = (const float*)d_in[5];
    const float* u     = (const float*)d_in[6];
    float* out = (float*)d_out;

    encode_kernel<<<ABLOCKS + BBLOCKS, EBLK>>>(
        x_num, x_cat, c_num, c_cat, c_y, delta, u);
    prep_kernel<<<(BITEMS + 255) / 256, 256>>>();
    nca_main_kernel<<<dim3(NQ / TQ, NCHUNKS), dim3(64, 4)>>>();
    finalize_kernel<<<(NQ * DOUT + 255) / 256, 256>>>(out);
}